// round 8
// baseline (speedup 1.0000x reference)
#include <cuda_runtime.h>
#include <cstdint>
#include <cstddef>

// Problem constants
#define Bsz 128
#define Tn  1024
#define Dn  64
#define Hn  256
#define On  128

// Partitioning: 16 clusters (batch groups) x 8 CTAs (column groups)
#define CLU  8
#define RGRP 16
#define BR   8      // batch rows per cluster
#define CN   32     // output columns per CTA
#define NTHREADS 256
#define K1W  40     // (D+H1)/8 warps
#define K2W  64     // (H1+H2)/8 warps
#define P1   68     // x tile pitch (floats), 272B (16B aligned)
#define P2   520    // h tile pitch (floats), 2080B (16B aligned): [h1 0:256 | h2 256:512 | pad]

#define H1_BYTES 8192   // inbound h1 per CTA per step (8 rows x 256 cols x 4B)
#define H2_BYTES 8192

// ---------------------------------------------------------------------------
// PTX helpers
// ---------------------------------------------------------------------------
__device__ __forceinline__ uint32_t smem_u32(const void* p) {
    uint32_t a;
    asm("{ .reg .u64 t; cvta.to.shared.u64 t, %1; cvt.u32.u64 %0, t; }" : "=r"(a) : "l"(p));
    return a;
}
__device__ __forceinline__ uint32_t ctarank() {
    uint32_t r; asm("mov.u32 %0, %%cluster_ctarank;" : "=r"(r)); return r;
}
__device__ __forceinline__ uint32_t mapa_u32(uint32_t addr, uint32_t rank) {
    uint32_t r;
    asm("mapa.shared::cluster.u32 %0, %1, %2;" : "=r"(r) : "r"(addr), "r"(rank));
    return r;
}
__device__ __forceinline__ void mbar_init(uint32_t addr, uint32_t cnt) {
    asm volatile("mbarrier.init.shared.b64 [%0], %1;" :: "r"(addr), "r"(cnt) : "memory");
}
__device__ __forceinline__ void mbar_arm(uint32_t addr, uint32_t bytes) {
    asm volatile("mbarrier.arrive.expect_tx.shared.b64 _, [%0], %1;"
                 :: "r"(addr), "r"(bytes) : "memory");
}
__device__ __forceinline__ void mbar_wait(uint32_t addr, uint32_t parity) {
    asm volatile(
        "{\n\t"
        ".reg .pred P1;\n\t"
        "WAIT_%=:\n\t"
        "mbarrier.try_wait.parity.acquire.cluster.shared::cta.b64 P1, [%0], %1, 0x989680;\n\t"
        "@P1 bra DONE_%=;\n\t"
        "bra WAIT_%=;\n\t"
        "DONE_%=:\n\t"
        "}"
        :: "r"(addr), "r"(parity) : "memory");
}
__device__ __forceinline__ void st_async_b64(uint32_t daddr, unsigned long long v, uint32_t mbar) {
    asm volatile("st.async.shared::cluster.mbarrier::complete_tx::bytes.b64 [%0], %1, [%2];"
                 :: "r"(daddr), "l"(v), "r"(mbar) : "memory");
}
__device__ __forceinline__ void cluster_sync_all() {
    asm volatile("barrier.cluster.arrive.aligned;" ::: "memory");
    asm volatile("barrier.cluster.wait.aligned;"   ::: "memory");
}
// packed fp32x2 fma
__device__ __forceinline__ void ffma2(unsigned long long& acc,
                                      unsigned long long a, unsigned long long w) {
    asm("fma.rn.f32x2 %0, %1, %2, %0;" : "+l"(acc) : "l"(a), "l"(w));
}
__device__ __forceinline__ float fast_tanh(float x) {
    float xc = fminf(fmaxf(x, -15.0f), 15.0f);
    float e = __expf(2.0f * xc);
    return __fdividef(e - 1.0f, e + 1.0f);
}

// ---------------------------------------------------------------------------
__global__ __launch_bounds__(NTHREADS, 1) __cluster_dims__(CLU, 1, 1)
void rnn_scan_kernel(const float* __restrict__ x,
                     const float* __restrict__ Wx1, const float* __restrict__ Wh1,
                     const float* __restrict__ b1,
                     const float* __restrict__ Wx2, const float* __restrict__ Wh2,
                     const float* __restrict__ b2,
                     const float* __restrict__ Wd,  const float* __restrict__ bd,
                     float* __restrict__ out)
{
    __shared__ __align__(16) float sX[2][BR][P1];     // x_t double buffer (4.3 KB)
    __shared__ __align__(16) float sH[2][BR][P2];     // [h1 | h2] parity buffers (33.3 KB)
    __shared__ __align__(16) float sRed[8][BR][CN];   // cross-warp partials (8 KB)
    __shared__ __align__(8)  unsigned long long sMbar[4]; // h1[p0],h1[p1],h2[p0],h2[p1]

    const int r   = blockIdx.x / CLU;          // batch group (cluster index)
    const uint32_t c = ctarank();              // column group within cluster
    const int rb0 = r * BR;
    const int tid = threadIdx.x;
    const int w   = tid >> 5;                  // warp = K-slice / row
    const int j   = tid & 31;                  // lane = column within CN
    const int jg  = (int)c * CN + j;           // global output column

    // ---- weights in registers, packed as consecutive-k f32 pairs ----
    unsigned long long wq1[K1W / 2];
#pragma unroll
    for (int i = 0; i < K1W / 2; i++) {
        int k0 = w * K1W + 2 * i, k1 = k0 + 1;
        float f0 = (k0 < Dn) ? __ldg(Wx1 + k0 * Hn + jg) : __ldg(Wh1 + (k0 - Dn) * Hn + jg);
        float f1_ = (k1 < Dn) ? __ldg(Wx1 + k1 * Hn + jg) : __ldg(Wh1 + (k1 - Dn) * Hn + jg);
        wq1[i] = ((unsigned long long)__float_as_uint(f1_) << 32) | __float_as_uint(f0);
    }
    // layer-2: warp w owns h1 ks [32w,32w+32) (wq2[0..15]) and h2 ks [256+32w,+32) (wq2[16..31])
    unsigned long long wq2[K2W / 2];
#pragma unroll
    for (int i = 0; i < 16; i++) {
        int k0 = 32 * w + 2 * i;
        float f0 = __ldg(Wx2 + k0 * Hn + jg), f1_ = __ldg(Wx2 + (k0 + 1) * Hn + jg);
        wq2[i] = ((unsigned long long)__float_as_uint(f1_) << 32) | __float_as_uint(f0);
    }
#pragma unroll
    for (int i = 0; i < 16; i++) {
        int k0 = 32 * w + 2 * i;
        float f0 = __ldg(Wh2 + k0 * Hn + jg), f1_ = __ldg(Wh2 + (k0 + 1) * Hn + jg);
        wq2[16 + i] = ((unsigned long long)__float_as_uint(f1_) << 32) | __float_as_uint(f0);
    }
    const float bias1 = __ldg(b1 + jg);
    const float bias2 = __ldg(b2 + jg);

    // ---- init: zero h state, stage x_1, init mbarriers, cluster sync ----
    for (int i = tid; i < 2 * BR * P2; i += NTHREADS) ((float*)sH)[i] = 0.0f;
    if (tid < 128) {
        int row = tid >> 4, c4 = tid & 15;
        float4 v = __ldg((const float4*)(x + ((size_t)(rb0 + row) * Tn + 0) * Dn + c4 * 4));
        *(float4*)&sX[1][row][c4 * 4] = v;     // parity of t=1
    }
    const uint32_t mbase = smem_u32(sMbar);
    const uint32_t hbase = smem_u32(sH);
    if (tid == 0) {
#pragma unroll
        for (int i = 0; i < 4; i++) mbar_init(mbase + i * 8, 1);
    }
    __syncthreads();
    cluster_sync_all();

    // peer base addresses (rank-mapped)
    uint32_t peerH[CLU], peerMB[CLU];
#pragma unroll
    for (int rk = 0; rk < CLU; rk++) {
        peerH[rk]  = mapa_u32(hbase, rk);
        peerMB[rk] = mapa_u32(mbase, rk);
    }

    for (int t = 1; t <= Tn; t++) {
        const int pPrev = (t - 1) & 1;
        const int pCur  = t & 1;

        // arm this step's inbound barriers (phase safety: previous phase of each
        // already completed via this CTA's own earlier waits)
        if (tid == 0) {
            mbar_arm(mbase + pCur * 8,      H1_BYTES);   // h1_t
            mbar_arm(mbase + 16 + pCur * 8, H2_BYTES);   // h2_t
        }

        // prefetch x_{t+1} (LDG issued before GEMM; STS after)
        float4 xn; int xrow = 0, xc4 = 0;
        const bool doX = (tid < 128) && (t < Tn);
        if (doX) {
            xrow = tid >> 4; xc4 = tid & 15;
            xn = __ldg((const float4*)(x + ((size_t)(rb0 + xrow) * Tn + t) * Dn + xc4 * 4));
        }

        // ---- layer-1 GEMM: x from sX[pCur], h1_{t-1} from sH[pPrev][0:256) ----
        unsigned long long acc[BR];
#pragma unroll
        for (int b_ = 0; b_ < BR; b_++) acc[b_] = 0ull;
        {
            const int kbase = w * K1W;
#pragma unroll
            for (int kc = 0; kc < K1W / 4; kc++) {
                const int k = kbase + kc * 4;
                const float* src; int str;
                if (k < Dn) { src = &sX[pCur][0][k];        str = P1; }
                else        { src = &sH[pPrev][0][k - Dn];  str = P2; }
                const unsigned long long w01 = wq1[2 * kc], w23 = wq1[2 * kc + 1];
#pragma unroll
                for (int b_ = 0; b_ < BR; b_++) {
                    ulonglong2 a = *(const ulonglong2*)src;   // broadcast LDS.128
                    ffma2(acc[b_], a.x, w01);
                    ffma2(acc[b_], a.y, w23);
                    src += str;
                }
            }
        }
        if (doX) *(float4*)&sX[pCur ^ 1][xrow][xc4 * 4] = xn;
#pragma unroll
        for (int b_ = 0; b_ < BR; b_++) {
            float2 f = *(float2*)&acc[b_];
            sRed[w][b_][j] = f.x + f.y;
        }
        __syncthreads();                                       // bar B

        // ---- reduce + tanh + broadcast h1_t to all 8 peers (DSMEM) ----
        {
            float v = bias1;
#pragma unroll
            for (int w2 = 0; w2 < 8; w2++) v += sRed[w2][w][j];
            v = fast_tanh(v);
            float vhi = __shfl_down_sync(0xffffffffu, v, 1);
            if ((j & 1) == 0) {
                unsigned long long pkt =
                    ((unsigned long long)__float_as_uint(vhi) << 32) | __float_as_uint(v);
                const uint32_t off = (uint32_t)(((pCur * BR + w) * P2 + jg) * 4);
                const uint32_t mb  = (uint32_t)(pCur * 8);
#pragma unroll
                for (int rk = 0; rk < CLU; rk++)
                    st_async_b64(peerH[rk] + off, pkt, peerMB[rk] + mb);
            }
        }

        // ---- layer-2, h2-half first (hides h1 exchange latency) ----
        if (t >= 2) mbar_wait(mbase + 16 + pPrev * 8, ((t - 2) >> 1) & 1);  // h2_{t-1}
#pragma unroll
        for (int b_ = 0; b_ < BR; b_++) acc[b_] = 0ull;
        {
            const float* base = &sH[pPrev][0][Hn + 32 * w];
#pragma unroll
            for (int kc = 0; kc < 8; kc++) {
                const float* src = base + kc * 4;
                const unsigned long long w01 = wq2[16 + 2 * kc], w23 = wq2[17 + 2 * kc];
#pragma unroll
                for (int b_ = 0; b_ < BR; b_++) {
                    ulonglong2 a = *(const ulonglong2*)src;
                    ffma2(acc[b_], a.x, w01);
                    ffma2(acc[b_], a.y, w23);
                    src += P2;
                }
            }
        }
        // ---- h1-half after h1_t arrives ----
        mbar_wait(mbase + pCur * 8, ((t - 1) >> 1) & 1);       // h1_t
        {
            const float* base = &sH[pCur][0][32 * w];
#pragma unroll
            for (int kc = 0; kc < 8; kc++) {
                const float* src = base + kc * 4;
                const unsigned long long w01 = wq2[2 * kc], w23 = wq2[2 * kc + 1];
#pragma unroll
                for (int b_ = 0; b_ < BR; b_++) {
                    ulonglong2 a = *(const ulonglong2*)src;
                    ffma2(acc[b_], a.x, w01);
                    ffma2(acc[b_], a.y, w23);
                    src += P2;
                }
            }
        }
        __syncthreads();                                       // bar C (sRed reuse)
#pragma unroll
        for (int b_ = 0; b_ < BR; b_++) {
            float2 f = *(float2*)&acc[b_];
            sRed[w][b_][j] = f.x + f.y;
        }
        __syncthreads();                                       // bar D

        // ---- reduce + tanh + broadcast h2_t ----
        {
            float v = bias2;
#pragma unroll
            for (int w2 = 0; w2 < 8; w2++) v += sRed[w2][w][j];
            v = fast_tanh(v);
            float vhi = __shfl_down_sync(0xffffffffu, v, 1);
            if ((j & 1) == 0) {
                unsigned long long pkt =
                    ((unsigned long long)__float_as_uint(vhi) << 32) | __float_as_uint(v);
                const uint32_t off = (uint32_t)(((pCur * BR + w) * P2 + Hn + jg) * 4);
                const uint32_t mb  = (uint32_t)(16 + pCur * 8);
#pragma unroll
                for (int rk = 0; rk < CLU; rk++)
                    st_async_b64(peerH[rk] + off, pkt, peerMB[rk] + mb);
            }
        }
        __syncthreads();                                       // bar A' (sRed + sX reuse)
    }

    // ------------------- Epilogue: dense + softmax (rank-0 CTA) -------------------
    if (c == 0) {
        // wait for h2_Tn (barrier h2[parity 0], use-index 511 -> parity 1)
        mbar_wait(mbase + 16 + 0 * 8, ((Tn - 2) >> 1) & 1);
        const int b_ = w;                 // warp = batch row
        float l0 = __ldg(bd + j);
        float l1 = __ldg(bd + j + 32);
        float l2_ = __ldg(bd + j + 64);
        float l3 = __ldg(bd + j + 96);
#pragma unroll 4
        for (int k = 0; k < Hn; k++) {
            const float hv = sH[0][b_][Hn + k];   // Tn even -> parity 0
            const float* wr = Wd + k * On;
            l0  = fmaf(hv, __ldg(wr + j),      l0);
            l1  = fmaf(hv, __ldg(wr + j + 32), l1);
            l2_ = fmaf(hv, __ldg(wr + j + 64), l2_);
            l3  = fmaf(hv, __ldg(wr + j + 96), l3);
        }
        float m = fmaxf(fmaxf(l0, l1), fmaxf(l2_, l3));
#pragma unroll
        for (int off = 16; off; off >>= 1) m = fmaxf(m, __shfl_xor_sync(0xffffffffu, m, off));
        const float e0 = expf(l0 - m);
        const float e1 = expf(l1 - m);
        const float e2 = expf(l2_ - m);
        const float e3 = expf(l3 - m);
        float s = e0 + e1 + e2 + e3;
#pragma unroll
        for (int off = 16; off; off >>= 1) s += __shfl_xor_sync(0xffffffffu, s, off);
        const float inv = 1.0f / s;
        float* o = out + (rb0 + b_) * On;
        o[j]      = e0 * inv;
        o[j + 32] = e1 * inv;
        o[j + 64] = e2 * inv;
        o[j + 96] = e3 * inv;
    }

    // keep cluster smem alive until all in-flight st.async delivered / consumed
    cluster_sync_all();
}

// ---------------------------------------------------------------------------
extern "C" void kernel_launch(void* const* d_in, const int* in_sizes, int n_in,
                              void* d_out, int out_size) {
    (void)in_sizes; (void)n_in; (void)out_size;
    const float* x   = (const float*)d_in[0];
    const float* Wx1 = (const float*)d_in[1];
    const float* Wh1 = (const float*)d_in[2];
    const float* b1  = (const float*)d_in[3];
    const float* Wx2 = (const float*)d_in[4];
    const float* Wh2 = (const float*)d_in[5];
    const float* b2  = (const float*)d_in[6];
    const float* Wd  = (const float*)d_in[7];
    const float* bd  = (const float*)d_in[8];
    float* out = (float*)d_out;

    rnn_scan_kernel<<<RGRP * CLU, NTHREADS>>>(x, Wx1, Wh1, b1, Wx2, Wh2, b2, Wd, bd, out);
}